// round 14
// baseline (speedup 1.0000x reference)
#include <cuda_runtime.h>
#include <cuda_fp16.h>
#include <math.h>
#include <stdint.h>

#define N_TOK  3584
#define N_SLOT 7168
#define DM     1024
#define NE     64
#define MAX_TILES 128

// FFN tiling: block 128x128, 8 warps (2x4), warp tile 64x32, BK=32, fp16 MMA
#define BM 128
#define BN 128
#define BK 32
#define NSTAGE 4
#define A_STAGE_B 10240        // 128 rows x 80B
#define B_STAGE_B 16896        // 32 rows x 528B
#define STAGE_B (A_STAGE_B + B_STAGE_B)            // 27136
#define SMEM_BYTES (NSTAGE*STAGE_B + BM*8 + BM*4 + 16)

// ---------------- device scratch ----------------
__device__ int    g_top2[N_SLOT];
__device__ int    g_order[N_SLOT];
__device__ int    g_tile_e[MAX_TILES];
__device__ int    g_tile_begin[MAX_TILES];
__device__ int    g_tile_m[MAX_TILES];
__device__ int    g_ntiles;
__device__ int    g_gate_cnt;                   // completed gate-gemm blocks
__device__ int    g_tile_cnt[MAX_TILES];        // completed ffn2 n-blocks per tile
__device__ __half g_h1h[(size_t)N_SLOT * DM];   // fp16 gelu(X@W1+b1)
__device__ __half g_xh[(size_t)N_TOK * DM];     // fp16 kept tokens
__device__ float  g_gwc[(size_t)NE * DM];       // ln_g * Wc per expert
__device__ float  g_sumgw[NE];                  // sum(ln_g*Wc)
__device__ float  g_dotbwc[NE];                 // sum(ln_b*Wc)
__device__ float  g_part[(size_t)N_SLOT * 8];   // per-slot partials

// ---------------- helpers ----------------
__device__ __forceinline__ void mma_f16(float* c, const uint32_t* a, const uint32_t* b) {
    asm volatile(
        "mma.sync.aligned.m16n8k16.row.col.f32.f16.f16.f32 "
        "{%0,%1,%2,%3}, {%4,%5,%6,%7}, {%8,%9}, {%0,%1,%2,%3};\n"
        : "+f"(c[0]), "+f"(c[1]), "+f"(c[2]), "+f"(c[3])
        : "r"(a[0]), "r"(a[1]), "r"(a[2]), "r"(a[3]), "r"(b[0]), "r"(b[1]));
}
__device__ __forceinline__ void cp16(uint32_t dst, const void* src, int bytes) {
    asm volatile("cp.async.cg.shared.global [%0], [%1], 16, %2;\n"
                 :: "r"(dst), "l"(src), "r"(bytes));
}
__device__ __forceinline__ void cp_commit() { asm volatile("cp.async.commit_group;\n"); }
template <int N>
__device__ __forceinline__ void cp_wait() { asm volatile("cp.async.wait_group %0;\n" :: "n"(N)); }
__device__ __forceinline__ float gelu_exact(float x) {
    return 0.5f * x * (1.f + erff(x * 0.70710678118654752f));
}
__device__ __forceinline__ uint32_t h2u(__half2 h) { return *(uint32_t*)&h; }

// ---------------- gate: GEMM+top2 (0..111) | const-prep (112..175) | fill (176..1199) ----------------
// Last finishing gemm block runs the build (histogram/scatter/tile table) inline.
__global__ __launch_bounds__(256) void gate_gemm(const float* __restrict__ inp,
                                                 const float* __restrict__ wg,
                                                 const float* __restrict__ ln_g,
                                                 const float* __restrict__ ln_b,
                                                 const float* __restrict__ Wc,
                                                 float* __restrict__ outbase,
                                                 float* __restrict__ conf_out,
                                                 float* __restrict__ prob_out) {
    int tid = threadIdx.x;
    if (blockIdx.x >= 176) {
        // batch-0 fill
        int r = blockIdx.x - 176;             // 0..1023
        const float4* src = (const float4*)(inp + (size_t)(r >> 1) * DM);
        float4* dst = (float4*)(outbase + (size_t)r * DM);
        dst[tid] = src[tid];
        if (tid == 0) { conf_out[r] = 0.f; prob_out[r] = 0.f; }
        return;
    }
    if (blockIdx.x >= 112) {
        // per-expert constants + partial zeroing (independent of gating)
        int e = blockIdx.x - 112;
        float* pz = g_part + (size_t)e * 112 * 8;
        for (int i = tid; i < 112 * 8; i += 256) pz[i] = 0.f;
        const float* gg = ln_g + (size_t)e * DM;
        const float* gb = ln_b + (size_t)e * DM;
        const float* wc = Wc   + (size_t)e * DM;
        float sgw = 0.f, bwc = 0.f;
        for (int d = tid; d < DM; d += 256) {
            float gw = gg[d] * wc[d];
            g_gwc[(size_t)e * DM + d] = gw;
            sgw += gw;
            bwc += gb[d] * wc[d];
        }
        __shared__ float sb[2][32];
        int lane = tid & 31, w = tid >> 5;
#pragma unroll
        for (int o = 16; o; o >>= 1) {
            sgw += __shfl_down_sync(0xffffffffu, sgw, o);
            bwc += __shfl_down_sync(0xffffffffu, bwc, o);
        }
        if (lane == 0) { sb[0][w] = sgw; sb[1][w] = bwc; }
        __syncthreads();
        if (tid == 0) {
            float a = 0.f, b = 0.f;
            for (int i = 0; i < 8; i++) { a += sb[0][i]; b += sb[1][i]; }
            g_sumgw[e] = a; g_dotbwc[e] = b;
        }
        return;
    }
    // ---- gate GEMM block ----
    int t0 = blockIdx.x * 32;
    __shared__ float Xs[32][33];
    __shared__ float Ws[32][65];
    __shared__ float Ls[32][65];
    __shared__ int s_last;
    int tx = tid & 15, ty = tid >> 4;
    float acc[2][4];
#pragma unroll
    for (int r = 0; r < 2; r++)
#pragma unroll
        for (int c = 0; c < 4; c++) acc[r][c] = 0.f;

    for (int k0 = 0; k0 < DM; k0 += 32) {
#pragma unroll
        for (int i = 0; i < 4; i++) {
            int lin = i * 256 + tid;
            int t = lin >> 5, k = lin & 31;
            float v = __ldg(inp + (size_t)(512 + t0 + t) * DM + k0 + k);
            Xs[k][t] = v;
            g_xh[(size_t)(t0 + t) * DM + k0 + k] = __float2half_rn(v);
        }
#pragma unroll
        for (int i = 0; i < 8; i++) {
            int lin = i * 256 + tid;
            int k = lin >> 6, e = lin & 63;
            Ws[k][e] = __ldg(wg + (size_t)(k0 + k) * NE + e);
        }
        __syncthreads();
#pragma unroll
        for (int kk = 0; kk < 32; kk++) {
            float a[2], b[4];
#pragma unroll
            for (int r = 0; r < 2; r++) a[r] = Xs[kk][ty * 2 + r];
#pragma unroll
            for (int c = 0; c < 4; c++) b[c] = Ws[kk][tx * 4 + c];
#pragma unroll
            for (int r = 0; r < 2; r++)
#pragma unroll
                for (int c = 0; c < 4; c++)
                    acc[r][c] = fmaf(a[r], b[c], acc[r][c]);
        }
        __syncthreads();
    }
#pragma unroll
    for (int r = 0; r < 2; r++)
#pragma unroll
        for (int c = 0; c < 4; c++)
            Ls[ty * 2 + r][tx * 4 + c] = acc[r][c];
    __syncthreads();

    int warp = tid >> 5, lane = tid & 31;
#pragma unroll
    for (int i = 0; i < 4; i++) {
        int t = warp * 4 + i;
        float x = Ls[t][lane], y = Ls[t][lane + 32];
        float a1, a2; int j1, j2;
        if (x >= y) { a1 = x; j1 = lane; a2 = y; j2 = lane + 32; }
        else        { a1 = y; j1 = lane + 32; a2 = x; j2 = lane; }
#pragma unroll
        for (int off = 16; off; off >>= 1) {
            float b1 = __shfl_xor_sync(0xffffffffu, a1, off);
            int   k1 = __shfl_xor_sync(0xffffffffu, j1, off);
            float b2 = __shfl_xor_sync(0xffffffffu, a2, off);
            int   k2 = __shfl_xor_sync(0xffffffffu, j2, off);
            if (b1 > a1) {
                float n2 = (a1 > b2) ? a1 : b2; int m2 = (a1 > b2) ? j1 : k2;
                a1 = b1; j1 = k1; a2 = n2; j2 = m2;
            } else if (b1 > a2) { a2 = b1; j2 = k1; }
        }
        if (lane == 0) {
            g_top2[2 * (t0 + t)]     = j1;
            g_top2[2 * (t0 + t) + 1] = j2;
        }
    }
    // ---- last gemm block runs the build ----
    __threadfence();
    __syncthreads();
    if (tid == 0) s_last = (atomicAdd(&g_gate_cnt, 1) == 111) ? 1 : 0;
    __syncthreads();
    if (!s_last) return;

    __shared__ int hist[NE];
    __shared__ int off[NE];
    __shared__ int cur[NE];
    if (tid == 0) g_gate_cnt = 0;                 // reset for next replay
    if (tid < NE) { hist[tid] = 0; cur[tid] = 0; }
    if (tid < MAX_TILES) g_tile_cnt[tid] = 0;
    __syncthreads();
    for (int s = tid; s < N_SLOT; s += 256)
        atomicAdd(&hist[g_top2[s]], 1);
    __syncthreads();
    if (tid == 0) {
        int acc2 = 0;
        for (int e = 0; e < NE; e++) { off[e] = acc2; acc2 += hist[e]; }
    }
    __syncthreads();
    for (int s = tid; s < N_SLOT; s += 256) {
        int e = g_top2[s];
        int p = atomicAdd(&cur[e], 1);
        g_order[off[e] + p] = s;
    }
    __syncthreads();
    if (tid == 0) {
        int nt = 0;
        for (int e = 0; e < NE; e++)
            for (int b = 0; b < hist[e]; b += BM) {
                g_tile_e[nt]     = e;
                g_tile_begin[nt] = off[e] + b;
                g_tile_m[nt]     = min(BM, hist[e] - b);
                nt++;
            }
        g_ntiles = nt;
    }
}

// ---------------- FP16 FFN: 128x128, BK=32, 4-stage cp.async, 2 CTAs/SM ----------------
// grid (n0_idx, tile); ffn2's last n-sibling per tile computes conf/prob from partials
template <bool FIRST>
__global__ __launch_bounds__(256, 2) void ffn_tc(
    const float* __restrict__ W,       // (E, D, D)
    const float* __restrict__ bias,    // (E, D)
    const float* __restrict__ Wp,      // (D, 2)
    const float* __restrict__ bc, const float* __restrict__ bp,
    const int*   __restrict__ y_label,
    float* __restrict__ outbase,
    float* __restrict__ conf_out, float* __restrict__ prob_out)
{
    int tile = blockIdx.y;
    if (tile >= g_ntiles) return;
    int e    = g_tile_e[tile];
    int mbeg = g_tile_begin[tile];
    int mcnt = g_tile_m[tile];
    int n0   = blockIdx.x * BN;

    extern __shared__ char smc[];
    const __half** s_arow = (const __half**)(smc + NSTAGE * STAGE_B);
    int* s_slot = (int*)(s_arow + BM);
    int* s_flag = s_slot + BM;

    int tid  = threadIdx.x;
    int lane = tid & 31, warp = tid >> 5;
    int g = lane >> 2, tg = lane & 3;
    int wm = warp >> 2, wn = warp & 3;                    // 2 x 4

    for (int m = tid; m < BM; m += 256) {
        int slot = (m < mcnt) ? g_order[mbeg + m] : -1;
        s_slot[m] = slot;
        const __half* p = nullptr;
        if (slot >= 0) {
            if (FIRST) {
                int tok = (slot >= N_TOK) ? slot - N_TOK : slot;
                p = g_xh + (size_t)tok * DM;
            } else {
                p = g_h1h + (size_t)slot * DM;
            }
        }
        s_arow[m] = p;
    }
    __syncthreads();

    const float* Wb = W + (size_t)e * DM * DM + n0;

    int ar = tid >> 1, aq = (tid & 1) * 2;
    const __half* arow = s_arow[ar];
    int asz = arow ? 16 : 0;
    const __half* asrc = arow ? arow + aq * 8 : (const __half*)W;
    int bk = tid >> 3, bq = tid & 7;
    const float* bsrc = Wb + (size_t)bk * DM + bq * 4;

    uint32_t smem_u32 = (uint32_t)__cvta_generic_to_shared(smc);
    uint32_t a_dst = smem_u32 + ar * 80 + aq * 16;
    uint32_t b_dst = smem_u32 + A_STAGE_B + bk * 528 + bq * 16;

#define ISSUE_STAGE(buf, step) do {                                       \
        uint32_t _off = (buf) * STAGE_B;                                  \
        int _k0 = (step) * BK;                                            \
        cp16(a_dst + _off,      asrc + _k0, asz);                         \
        cp16(a_dst + _off + 16, asrc + _k0 + 8, asz);                     \
        const float* _bs = bsrc + (size_t)_k0 * DM;                       \
        cp16(b_dst + _off,       _bs,       16);                          \
        cp16(b_dst + _off + 128, _bs + 32,  16);                          \
        cp16(b_dst + _off + 256, _bs + 64,  16);                          \
        cp16(b_dst + _off + 384, _bs + 96,  16);                          \
        cp_commit();                                                      \
    } while (0)

#define MMA_STAGE(buf) do {                                               \
        const __half* Ah = (const __half*)(smc + (buf) * STAGE_B);        \
        const float*  Bf = (const float*)(smc + (buf) * STAGE_B + A_STAGE_B); \
        _Pragma("unroll")                                                 \
        for (int kc = 0; kc < 2; kc++) {                                  \
            uint32_t a[4][4];                                             \
            _Pragma("unroll")                                             \
            for (int mt = 0; mt < 4; mt++) {                              \
                const __half* ap = Ah + (wm * 64 + mt * 16 + g) * 40 + kc * 16 + tg * 2; \
                a[mt][0] = *(const uint32_t*)(ap);                        \
                a[mt][1] = *(const uint32_t*)(ap + 8 * 40);               \
                a[mt][2] = *(const uint32_t*)(ap + 8);                    \
                a[mt][3] = *(const uint32_t*)(ap + 8 * 40 + 8);           \
            }                                                             \
            _Pragma("unroll")                                             \
            for (int nt = 0; nt < 4; nt++) {                              \
                int col = wn * 32 + nt * 8 + g;                           \
                const float* bp2 = Bf + (kc * 16 + 2 * tg) * 132 + col;   \
                uint32_t b[2];                                            \
                b[0] = h2u(__floats2half2_rn(bp2[0],       bp2[132]));    \
                b[1] = h2u(__floats2half2_rn(bp2[8 * 132], bp2[9 * 132]));\
                _Pragma("unroll")                                         \
                for (int mt = 0; mt < 4; mt++)                            \
                    mma_f16(acc[mt][nt], a[mt], b);                       \
            }                                                             \
        }                                                                 \
    } while (0)

    float acc[4][4][4];
#pragma unroll
    for (int mt = 0; mt < 4; mt++)
#pragma unroll
        for (int nt = 0; nt < 4; nt++)
#pragma unroll
            for (int i = 0; i < 4; i++) acc[mt][nt][i] = 0.f;

    ISSUE_STAGE(0, 0); ISSUE_STAGE(1, 1); ISSUE_STAGE(2, 2);

    const int NSTEPK = DM / BK;   // 32
    int buf = 0, ibuf = 3;
#pragma unroll 1
    for (int s = 0; s < NSTEPK; s++) {
        cp_wait<2>();
        __syncthreads();
        if (s + 3 < NSTEPK) ISSUE_STAGE(ibuf, s + 3);
        else cp_commit();
        MMA_STAGE(buf);
        buf  = (buf  == NSTAGE - 1) ? 0 : buf  + 1;
        ibuf = (ibuf == NSTAGE - 1) ? 0 : ibuf + 1;
    }
#undef ISSUE_STAGE
#undef MMA_STAGE

    const float* bptr = bias + (size_t)e * DM;
    if (FIRST) {
#pragma unroll
        for (int nt = 0; nt < 4; nt++) {
            int col = n0 + wn * 32 + nt * 8 + tg * 2;
            float2 bv = *(const float2*)(bptr + col);
#pragma unroll
            for (int mt = 0; mt < 4; mt++) {
                int ml = wm * 64 + mt * 16 + g;
                int s0 = s_slot[ml], s1 = s_slot[ml + 8];
                float* c = acc[mt][nt];
                if (s0 >= 0)
                    *(__half2*)&g_h1h[(size_t)s0 * DM + col] =
                        __floats2half2_rn(gelu_exact(c[0] + bv.x), gelu_exact(c[1] + bv.y));
                if (s1 >= 0)
                    *(__half2*)&g_h1h[(size_t)s1 * DM + col] =
                        __floats2half2_rn(gelu_exact(c[2] + bv.x), gelu_exact(c[3] + bv.y));
            }
        }
    } else {
        const float* gwc = g_gwc + (size_t)e * DM;
#pragma unroll
        for (int mt = 0; mt < 4; mt++) {
#pragma unroll
            for (int half = 0; half < 2; half++) {
                int ml = wm * 64 + mt * 16 + g + half * 8;
                int slot = s_slot[ml];
                float* dst = (slot >= 0) ? (outbase + (size_t)(slot + 1024) * DM) : nullptr;
                float ph = 0.f, ph2 = 0.f, pgw = 0.f, pz0 = 0.f, pz1 = 0.f;
#pragma unroll
                for (int nt = 0; nt < 4; nt++) {
                    int col = n0 + wn * 32 + nt * 8 + tg * 2;
                    float2 bv = *(const float2*)(bptr + col);
                    float h0 = acc[mt][nt][half * 2]     + bv.x;
                    float h1 = acc[mt][nt][half * 2 + 1] + bv.y;
                    if (dst) { float2 o; o.x = h0; o.y = h1; *(float2*)(dst + col) = o; }
                    float2 gw = *(const float2*)(gwc + col);
                    float4 wp = *(const float4*)(Wp + col * 2);
                    ph  += h0 + h1;
                    ph2 += h0 * h0 + h1 * h1;
                    pgw += h0 * gw.x + h1 * gw.y;
                    pz0 += h0 * wp.x + h1 * wp.z;
                    pz1 += h0 * wp.y + h1 * wp.w;
                }
#pragma unroll
                for (int o = 1; o < 4; o <<= 1) {
                    ph  += __shfl_xor_sync(0xffffffffu, ph,  o);
                    ph2 += __shfl_xor_sync(0xffffffffu, ph2, o);
                    pgw += __shfl_xor_sync(0xffffffffu, pgw, o);
                    pz0 += __shfl_xor_sync(0xffffffffu, pz0, o);
                    pz1 += __shfl_xor_sync(0xffffffffu, pz1, o);
                }
                if (slot >= 0 && tg == 0) {
                    float* pp = g_part + (size_t)slot * 8;
                    atomicAdd(pp,     ph);
                    atomicAdd(pp + 1, ph2);
                    atomicAdd(pp + 2, pgw);
                    atomicAdd(pp + 3, pz0);
                    atomicAdd(pp + 4, pz1);
                }
            }
        }
        // ---- last n-sibling of this tile computes conf/prob ----
        __threadfence();
        __syncthreads();
        if (tid == 0) *s_flag = (atomicAdd(&g_tile_cnt[tile], 1) == 7) ? 1 : 0;
        __syncthreads();
        if (*s_flag && tid < BM) {
            int slot = s_slot[tid];
            if (slot >= 0) {
                int ee = g_top2[slot];
                const float* pp = g_part + (size_t)slot * 8;
                float ph = pp[0], ph2 = pp[1], pgw = pp[2], z0 = pp[3], z1 = pp[4];
                float mu  = ph * (1.f / 1024.f);
                float var = ph2 * (1.f / 1024.f) - mu * mu;
                float inv = rsqrtf(var + 1e-5f);
                float cval = inv * (pgw - mu * g_sumgw[ee]) + g_dotbwc[ee] + bc[ee];
                float conf = 1.f / (1.f + expf(-cval));
                z0 += bp[0]; z1 += bp[1];
                float mx = fmaxf(z0, z1);
                float e0 = expf(z0 - mx), e1 = expf(z1 - mx);
                int y = y_label[(slot >> 10) + 1];
                float pr = ((y == 0) ? e0 : e1) / (e0 + e1);
                conf_out[slot + 1024] = conf;
                prob_out[slot + 1024] = pr;
            }
        }
    }
}

// ---------------- launch ----------------
extern "C" void kernel_launch(void* const* d_in, const int* in_sizes, int n_in,
                              void* d_out, int out_size) {
    const float* inp     = (const float*)d_in[0];
    const int*   y_label = (const int*)  d_in[2];
    const float* w_gate  = (const float*)d_in[3];
    const float* W1      = (const float*)d_in[4];
    const float* b1      = (const float*)d_in[5];
    const float* W2      = (const float*)d_in[6];
    const float* b2      = (const float*)d_in[7];
    const float* ln_g    = (const float*)d_in[8];
    const float* ln_b    = (const float*)d_in[9];
    const float* Wc      = (const float*)d_in[10];
    const float* bc      = (const float*)d_in[11];
    const float* Wp      = (const float*)d_in[12];
    const float* bp      = (const float*)d_in[13];

    float* out      = (float*)d_out;
    float* conf_out = out + (size_t)8 * 512 * 2 * 1024;
    float* prob_out = conf_out + 8 * 512 * 2;

    static bool attr_done = false;
    if (!attr_done) {
        cudaFuncSetAttribute(ffn_tc<true>,  cudaFuncAttributeMaxDynamicSharedMemorySize, SMEM_BYTES);
        cudaFuncSetAttribute(ffn_tc<false>, cudaFuncAttributeMaxDynamicSharedMemorySize, SMEM_BYTES);
        attr_done = true;
    }

    gate_gemm<<<176 + 1024, 256>>>(inp, w_gate, ln_g, ln_b, Wc, out, conf_out, prob_out);
    ffn_tc<true ><<<dim3(8, MAX_TILES), 256, SMEM_BYTES>>>(W1, b1, Wp, bc, bp, y_label,
                                                           out, conf_out, prob_out);
    ffn_tc<false><<<dim3(8, MAX_TILES), 256, SMEM_BYTES>>>(W2, b2, Wp, bc, bp, y_label,
                                                           out, conf_out, prob_out);
}

// round 15
// speedup vs baseline: 1.0861x; 1.0861x over previous
#include <cuda_runtime.h>
#include <cuda_fp16.h>
#include <math.h>
#include <stdint.h>

#define N_TOK  3584
#define N_SLOT 7168
#define DM     1024
#define NE     64
#define MAX_TILES 128

// FFN tiling: block 128x128, 8 warps (2x4), warp tile 64x32, BK=32, fp16 MMA
#define BM 128
#define BN 128
#define BK 32
#define NSTAGE 4
#define A_STAGE_B 10240        // 128 rows x 80B
#define B_STAGE_B 16896        // 32 rows x 528B
#define STAGE_B (A_STAGE_B + B_STAGE_B)            // 27136
#define SMEM_BYTES (NSTAGE*STAGE_B + BM*8 + BM*4)  // 110080

// ---------------- device scratch ----------------
__device__ int    g_top2[N_SLOT];
__device__ int    g_order[N_SLOT];
__device__ int    g_tile_e[MAX_TILES];
__device__ int    g_tile_begin[MAX_TILES];
__device__ int    g_tile_m[MAX_TILES];
__device__ int    g_ntiles;
__device__ __half g_h1h[(size_t)N_SLOT * DM];   // fp16 gelu(X@W1+b1)
__device__ __half g_xh[(size_t)N_TOK * DM];     // fp16 kept tokens
__device__ float  g_gwc[(size_t)NE * DM];       // ln_g * Wc per expert
__device__ float  g_sumgw[NE];                  // sum(ln_g*Wc)
__device__ float  g_dotbwc[NE];                 // sum(ln_b*Wc)
__device__ float  g_part[(size_t)N_SLOT * 8];   // per-slot partials

// ---------------- helpers ----------------
__device__ __forceinline__ void mma_f16(float* c, const uint32_t* a, const uint32_t* b) {
    asm volatile(
        "mma.sync.aligned.m16n8k16.row.col.f32.f16.f16.f32 "
        "{%0,%1,%2,%3}, {%4,%5,%6,%7}, {%8,%9}, {%0,%1,%2,%3};\n"
        : "+f"(c[0]), "+f"(c[1]), "+f"(c[2]), "+f"(c[3])
        : "r"(a[0]), "r"(a[1]), "r"(a[2]), "r"(a[3]), "r"(b[0]), "r"(b[1]));
}
__device__ __forceinline__ void cp16(uint32_t dst, const void* src, int bytes) {
    asm volatile("cp.async.cg.shared.global [%0], [%1], 16, %2;\n"
                 :: "r"(dst), "l"(src), "r"(bytes));
}
__device__ __forceinline__ void cp_commit() { asm volatile("cp.async.commit_group;\n"); }
template <int N>
__device__ __forceinline__ void cp_wait() { asm volatile("cp.async.wait_group %0;\n" :: "n"(N)); }
__device__ __forceinline__ float gelu_exact(float x) {
    return 0.5f * x * (1.f + erff(x * 0.70710678118654752f));
}
__device__ __forceinline__ uint32_t h2u(__half2 h) { return *(uint32_t*)&h; }

// ---------------- gate GEMM (224 blocks x 16 tokens) + top-2 + fp16 copy + fill ----------------
__global__ __launch_bounds__(256) void gate_gemm(const float* __restrict__ inp,
                                                 const float* __restrict__ wg,
                                                 float* __restrict__ outbase,
                                                 float* __restrict__ conf_out,
                                                 float* __restrict__ prob_out) {
    int tid = threadIdx.x;
    if (blockIdx.x >= 224) {
        int r = blockIdx.x - 224;             // 0..1023
        const float4* src = (const float4*)(inp + (size_t)(r >> 1) * DM);
        float4* dst = (float4*)(outbase + (size_t)r * DM);
        dst[tid] = src[tid];
        if (tid == 0) { conf_out[r] = 0.f; prob_out[r] = 0.f; }
        return;
    }
    int t0 = blockIdx.x * 16;
    __shared__ float Xs[32][17];              // [k][token]
    __shared__ float Ws[32][68];              // [k][expert], stride 68 (272B, 16B-aligned)
    __shared__ float Ls[16][65];
    int tx = tid & 15, ty = tid >> 4;         // thread: token ty, experts 4*tx..4*tx+3
    float acc[4] = {0.f, 0.f, 0.f, 0.f};

    for (int k0 = 0; k0 < DM; k0 += 32) {
#pragma unroll
        for (int i = 0; i < 2; i++) {         // 16 tok x 32 k
            int lin = i * 256 + tid;
            int t = lin >> 5, k = lin & 31;
            float v = __ldg(inp + (size_t)(512 + t0 + t) * DM + k0 + k);
            Xs[k][t] = v;
            g_xh[(size_t)(t0 + t) * DM + k0 + k] = __float2half_rn(v);
        }
#pragma unroll
        for (int i = 0; i < 8; i++) {         // 32 k x 64 e
            int lin = i * 256 + tid;
            int k = lin >> 6, e = lin & 63;
            Ws[k][e] = __ldg(wg + (size_t)(k0 + k) * NE + e);
        }
        __syncthreads();
#pragma unroll
        for (int kk = 0; kk < 32; kk++) {
            float a = Xs[kk][ty];
            float4 b = *(const float4*)&Ws[kk][tx * 4];
            acc[0] = fmaf(a, b.x, acc[0]);
            acc[1] = fmaf(a, b.y, acc[1]);
            acc[2] = fmaf(a, b.z, acc[2]);
            acc[3] = fmaf(a, b.w, acc[3]);
        }
        __syncthreads();
    }
#pragma unroll
    for (int c = 0; c < 4; c++) Ls[ty][tx * 4 + c] = acc[c];
    __syncthreads();

    // top-2: 8 warps x 2 tokens
    int warp = tid >> 5, lane = tid & 31;
#pragma unroll
    for (int i = 0; i < 2; i++) {
        int t = warp * 2 + i;
        float x = Ls[t][lane], y = Ls[t][lane + 32];
        float a1, a2; int j1, j2;
        if (x >= y) { a1 = x; j1 = lane; a2 = y; j2 = lane + 32; }
        else        { a1 = y; j1 = lane + 32; a2 = x; j2 = lane; }
#pragma unroll
        for (int off = 16; off; off >>= 1) {
            float b1 = __shfl_xor_sync(0xffffffffu, a1, off);
            int   k1 = __shfl_xor_sync(0xffffffffu, j1, off);
            float b2 = __shfl_xor_sync(0xffffffffu, a2, off);
            int   k2 = __shfl_xor_sync(0xffffffffu, j2, off);
            if (b1 > a1) {
                float n2 = (a1 > b2) ? a1 : b2; int m2 = (a1 > b2) ? j1 : k2;
                a1 = b1; j1 = k1; a2 = n2; j2 = m2;
            } else if (b1 > a2) { a2 = b1; j2 = k1; }
        }
        if (lane == 0) {
            g_top2[2 * (t0 + t)]     = j1;
            g_top2[2 * (t0 + t) + 1] = j2;
        }
    }
}

// ---------------- build (block 0) + per-expert constants (blocks 1..64) ----------------
__global__ __launch_bounds__(256) void build_kernel(const float* __restrict__ ln_g,
                                                    const float* __restrict__ ln_b,
                                                    const float* __restrict__ Wc) {
    int tid = threadIdx.x;
    if (blockIdx.x > 0) {
        int e = blockIdx.x - 1;
        float* pz = g_part + (size_t)e * 112 * 8;
        for (int i = tid; i < 112 * 8; i += 256) pz[i] = 0.f;
        const float* gg = ln_g + (size_t)e * DM;
        const float* gb = ln_b + (size_t)e * DM;
        const float* wc = Wc   + (size_t)e * DM;
        float sgw = 0.f, bwc = 0.f;
        for (int d = tid; d < DM; d += 256) {
            float gw = gg[d] * wc[d];
            g_gwc[(size_t)e * DM + d] = gw;
            sgw += gw;
            bwc += gb[d] * wc[d];
        }
        __shared__ float sb[2][32];
        int lane = tid & 31, w = tid >> 5;
#pragma unroll
        for (int o = 16; o; o >>= 1) {
            sgw += __shfl_down_sync(0xffffffffu, sgw, o);
            bwc += __shfl_down_sync(0xffffffffu, bwc, o);
        }
        if (lane == 0) { sb[0][w] = sgw; sb[1][w] = bwc; }
        __syncthreads();
        if (tid == 0) {
            float a = 0.f, b = 0.f;
            for (int i = 0; i < 8; i++) { a += sb[0][i]; b += sb[1][i]; }
            g_sumgw[e] = a; g_dotbwc[e] = b;
        }
        return;
    }
    __shared__ int hist[NE];
    __shared__ int off[NE];
    __shared__ int cur[NE];
    if (tid < NE) { hist[tid] = 0; cur[tid] = 0; }
    __syncthreads();
    for (int s = tid; s < N_SLOT; s += blockDim.x)
        atomicAdd(&hist[g_top2[s]], 1);
    __syncthreads();
    if (tid == 0) {
        int acc = 0;
        for (int e = 0; e < NE; e++) { off[e] = acc; acc += hist[e]; }
    }
    __syncthreads();
    for (int s = tid; s < N_SLOT; s += blockDim.x) {
        int e = g_top2[s];
        int p = atomicAdd(&cur[e], 1);
        g_order[off[e] + p] = s;
    }
    __syncthreads();
    if (tid == 0) {
        int nt = 0;
        for (int e = 0; e < NE; e++)
            for (int b = 0; b < hist[e]; b += BM) {
                g_tile_e[nt]     = e;
                g_tile_begin[nt] = off[e] + b;
                g_tile_m[nt]     = min(BM, hist[e] - b);
                nt++;
            }
        g_ntiles = nt;
    }
}

// ---------------- FP16 FFN: 128x128, BK=32, 4-stage cp.async, 2 CTAs/SM ----------------
// grid: (n0_idx, tile) so n-siblings share the A tile + expert B in L2
template <bool FIRST>
__global__ __launch_bounds__(256, 2) void ffn_tc(
    const float* __restrict__ W,       // (E, D, D)
    const float* __restrict__ bias,    // (E, D)
    const float* __restrict__ Wp,      // (D, 2) — used when !FIRST
    float* __restrict__ outbase)
{
    int tile = blockIdx.y;
    if (tile >= g_ntiles) return;
    int e    = g_tile_e[tile];
    int mbeg = g_tile_begin[tile];
    int mcnt = g_tile_m[tile];
    int n0   = blockIdx.x * BN;

    extern __shared__ char smc[];
    const __half** s_arow = (const __half**)(smc + NSTAGE * STAGE_B);
    int* s_slot = (int*)(s_arow + BM);

    int tid  = threadIdx.x;
    int lane = tid & 31, warp = tid >> 5;
    int g = lane >> 2, tg = lane & 3;
    int wm = warp >> 2, wn = warp & 3;                    // 2 x 4

    for (int m = tid; m < BM; m += 256) {
        int slot = (m < mcnt) ? g_order[mbeg + m] : -1;
        s_slot[m] = slot;
        const __half* p = nullptr;
        if (slot >= 0) {
            if (FIRST) {
                int tok = (slot >= N_TOK) ? slot - N_TOK : slot;
                p = g_xh + (size_t)tok * DM;
            } else {
                p = g_h1h + (size_t)slot * DM;
            }
        }
        s_arow[m] = p;
    }
    __syncthreads();

    const float* Wb = W + (size_t)e * DM * DM + n0;

    int ar = tid >> 1, aq = (tid & 1) * 2;
    const __half* arow = s_arow[ar];
    int asz = arow ? 16 : 0;
    const __half* asrc = arow ? arow + aq * 8 : (const __half*)W;
    int bk = tid >> 3, bq = tid & 7;
    const float* bsrc = Wb + (size_t)bk * DM + bq * 4;

    uint32_t smem_u32 = (uint32_t)__cvta_generic_to_shared(smc);
    uint32_t a_dst = smem_u32 + ar * 80 + aq * 16;
    uint32_t b_dst = smem_u32 + A_STAGE_B + bk * 528 + bq * 16;

#define ISSUE_STAGE(buf, step) do {                                       \
        uint32_t _off = (buf) * STAGE_B;                                  \
        int _k0 = (step) * BK;                                            \
        cp16(a_dst + _off,      asrc + _k0, asz);                         \
        cp16(a_dst + _off + 16, asrc + _k0 + 8, asz);                     \
        const float* _bs = bsrc + (size_t)_k0 * DM;                       \
        cp16(b_dst + _off,       _bs,       16);                          \
        cp16(b_dst + _off + 128, _bs + 32,  16);                          \
        cp16(b_dst + _off + 256, _bs + 64,  16);                          \
        cp16(b_dst + _off + 384, _bs + 96,  16);                          \
        cp_commit();                                                      \
    } while (0)

#define MMA_STAGE(buf) do {                                               \
        const __half* Ah = (const __half*)(smc + (buf) * STAGE_B);        \
        const float*  Bf = (const float*)(smc + (buf) * STAGE_B + A_STAGE_B); \
        _Pragma("unroll")                                                 \
        for (int kc = 0; kc < 2; kc++) {                                  \
            uint32_t a[4][4];                                             \
            _Pragma("unroll")                                             \
            for (int mt = 0; mt < 4; mt++) {                              \
                const __half* ap = Ah + (wm * 64 + mt * 16 + g) * 40 + kc * 16 + tg * 2; \
                a[mt][0] = *(const uint32_t*)(ap);                        \
                a[mt][1] = *(const uint32_t*)(ap + 8 * 40);               \
                a[mt][2] = *(const uint32_t*)(ap + 8);                    \
                a[mt][3] = *(const uint32_t*)(ap + 8 * 40 + 8);           \
            }                                                             \
            _Pragma("unroll")                                             \
            for (int nt = 0; nt < 4; nt++) {                              \
                int col = wn * 32 + nt * 8 + g;                           \
                const float* bp = Bf + (kc * 16 + 2 * tg) * 132 + col;    \
                uint32_t b[2];                                            \
                b[0] = h2u(__floats2half2_rn(bp[0],       bp[132]));      \
                b[1] = h2u(__floats2half2_rn(bp[8 * 132], bp[9 * 132]));  \
                _Pragma("unroll")                                         \
                for (int mt = 0; mt < 4; mt++)                            \
                    mma_f16(acc[mt][nt], a[mt], b);                       \
            }                                                             \
        }                                                                 \
    } while (0)

    float acc[4][4][4];
#pragma unroll
    for (int mt = 0; mt < 4; mt++)
#pragma unroll
        for (int nt = 0; nt < 4; nt++)
#pragma unroll
            for (int i = 0; i < 4; i++) acc[mt][nt][i] = 0.f;

    ISSUE_STAGE(0, 0); ISSUE_STAGE(1, 1); ISSUE_STAGE(2, 2);

    const int NSTEPK = DM / BK;   // 32
    int buf = 0, ibuf = 3;
#pragma unroll 1
    for (int s = 0; s < NSTEPK; s++) {
        cp_wait<2>();
        __syncthreads();
        if (s + 3 < NSTEPK) ISSUE_STAGE(ibuf, s + 3);
        else cp_commit();
        MMA_STAGE(buf);
        buf  = (buf  == NSTAGE - 1) ? 0 : buf  + 1;
        ibuf = (ibuf == NSTAGE - 1) ? 0 : ibuf + 1;
    }
#undef ISSUE_STAGE
#undef MMA_STAGE

    const float* bptr = bias + (size_t)e * DM;
    if (FIRST) {
#pragma unroll
        for (int nt = 0; nt < 4; nt++) {
            int col = n0 + wn * 32 + nt * 8 + tg * 2;
            float2 bv = *(const float2*)(bptr + col);
#pragma unroll
            for (int mt = 0; mt < 4; mt++) {
                int ml = wm * 64 + mt * 16 + g;
                int s0 = s_slot[ml], s1 = s_slot[ml + 8];
                float* c = acc[mt][nt];
                if (s0 >= 0)
                    *(__half2*)&g_h1h[(size_t)s0 * DM + col] =
                        __floats2half2_rn(gelu_exact(c[0] + bv.x), gelu_exact(c[1] + bv.y));
                if (s1 >= 0)
                    *(__half2*)&g_h1h[(size_t)s1 * DM + col] =
                        __floats2half2_rn(gelu_exact(c[2] + bv.x), gelu_exact(c[3] + bv.y));
            }
        }
    } else {
        const float* gwc = g_gwc + (size_t)e * DM;
#pragma unroll
        for (int mt = 0; mt < 4; mt++) {
#pragma unroll
            for (int half = 0; half < 2; half++) {
                int ml = wm * 64 + mt * 16 + g + half * 8;
                int slot = s_slot[ml];
                float* dst = (slot >= 0) ? (outbase + (size_t)(slot + 1024) * DM) : nullptr;
                float ph = 0.f, ph2 = 0.f, pgw = 0.f, pz0 = 0.f, pz1 = 0.f;
#pragma unroll
                for (int nt = 0; nt < 4; nt++) {
                    int col = n0 + wn * 32 + nt * 8 + tg * 2;
                    float2 bv = *(const float2*)(bptr + col);
                    float h0 = acc[mt][nt][half * 2]     + bv.x;
                    float h1 = acc[mt][nt][half * 2 + 1] + bv.y;
                    if (dst) { float2 o; o.x = h0; o.y = h1; *(float2*)(dst + col) = o; }
                    float2 gw = *(const float2*)(gwc + col);
                    float4 wp = *(const float4*)(Wp + col * 2);
                    ph  += h0 + h1;
                    ph2 += h0 * h0 + h1 * h1;
                    pgw += h0 * gw.x + h1 * gw.y;
                    pz0 += h0 * wp.x + h1 * wp.z;
                    pz1 += h0 * wp.y + h1 * wp.w;
                }
#pragma unroll
                for (int o = 1; o < 4; o <<= 1) {
                    ph  += __shfl_xor_sync(0xffffffffu, ph,  o);
                    ph2 += __shfl_xor_sync(0xffffffffu, ph2, o);
                    pgw += __shfl_xor_sync(0xffffffffu, pgw, o);
                    pz0 += __shfl_xor_sync(0xffffffffu, pz0, o);
                    pz1 += __shfl_xor_sync(0xffffffffu, pz1, o);
                }
                if (slot >= 0 && tg == 0) {
                    float* pp = g_part + (size_t)slot * 8;
                    atomicAdd(pp,     ph);
                    atomicAdd(pp + 1, ph2);
                    atomicAdd(pp + 2, pgw);
                    atomicAdd(pp + 3, pz0);
                    atomicAdd(pp + 4, pz1);
                }
            }
        }
    }
}

// ---------------- finish: conf + prob from partials ----------------
__global__ __launch_bounds__(256) void finish_kernel(
    const float* __restrict__ bc, const float* __restrict__ bp,
    const int* __restrict__ y_label,
    float* __restrict__ conf_out, float* __restrict__ prob_out)
{
    int slot = blockIdx.x * 256 + threadIdx.x;
    if (slot >= N_SLOT) return;
    int e = g_top2[slot];
    const float* pp = g_part + (size_t)slot * 8;
    float ph = pp[0], ph2 = pp[1], pgw = pp[2], z0 = pp[3], z1 = pp[4];
    float mu  = ph * (1.f / 1024.f);
    float var = ph2 * (1.f / 1024.f) - mu * mu;
    float inv = rsqrtf(var + 1e-5f);
    float cval = inv * (pgw - mu * g_sumgw[e]) + g_dotbwc[e] + bc[e];
    float conf = 1.f / (1.f + expf(-cval));
    z0 += bp[0]; z1 += bp[1];
    float mx = fmaxf(z0, z1);
    float e0 = expf(z0 - mx), e1 = expf(z1 - mx);
    int y = y_label[(slot >> 10) + 1];
    float pr = ((y == 0) ? e0 : e1) / (e0 + e1);
    conf_out[slot + 1024] = conf;
    prob_out[slot + 1024] = pr;
}

// ---------------- launch ----------------
extern "C" void kernel_launch(void* const* d_in, const int* in_sizes, int n_in,
                              void* d_out, int out_size) {
    const float* inp     = (const float*)d_in[0];
    const int*   y_label = (const int*)  d_in[2];
    const float* w_gate  = (const float*)d_in[3];
    const float* W1      = (const float*)d_in[4];
    const float* b1      = (const float*)d_in[5];
    const float* W2      = (const float*)d_in[6];
    const float* b2      = (const float*)d_in[7];
    const float* ln_g    = (const float*)d_in[8];
    const float* ln_b    = (const float*)d_in[9];
    const float* Wc      = (const float*)d_in[10];
    const float* bc      = (const float*)d_in[11];
    const float* Wp      = (const float*)d_in[12];
    const float* bp      = (const float*)d_in[13];

    float* out      = (float*)d_out;
    float* conf_out = out + (size_t)8 * 512 * 2 * 1024;
    float* prob_out = conf_out + 8 * 512 * 2;

    static bool attr_done = false;
    if (!attr_done) {
        cudaFuncSetAttribute(ffn_tc<true>,  cudaFuncAttributeMaxDynamicSharedMemorySize, SMEM_BYTES);
        cudaFuncSetAttribute(ffn_tc<false>, cudaFuncAttributeMaxDynamicSharedMemorySize, SMEM_BYTES);
        attr_done = true;
    }

    gate_gemm<<<224 + 1024, 256>>>(inp, w_gate, out, conf_out, prob_out);
    build_kernel<<<65, 256>>>(ln_g, ln_b, Wc);
    ffn_tc<true ><<<dim3(8, MAX_TILES), 256, SMEM_BYTES>>>(W1, b1, Wp, out);
    ffn_tc<false><<<dim3(8, MAX_TILES), 256, SMEM_BYTES>>>(W2, b2, Wp, out);
    finish_kernel<<<(N_SLOT + 255) / 256, 256>>>(bc, bp, y_label, conf_out, prob_out);
}